// round 3
// baseline (speedup 1.0000x reference)
#include <cuda_runtime.h>
#include <cuda_fp16.h>
#include <math.h>
#include <stdint.h>

#define BB   32
#define TT   512
#define SS   512
#define DD   1024
#define MM   10
#define K3   3072
#define KP   3080      // padded K stride (halves) for Ws: conflict-free B-frag loads
#define NCTA 128
#define NTHR 256

// ---------------- static device scratch (allocations are forbidden) ----------------
__device__ __half  g_in[BB * TT * DD];        // fp16 copy of input_h_c
__device__ __half  g_mem[BB * SS * DD];       // fp16 copy of memory
__device__ __half  g_ctx[BB * DD];            // ctx_{t} (fp16), produced by phase C
__device__ __half  g_h[2][BB * DD];           // double-buffered h (fp16)
__device__ float   g_phipart[NCTA][BB][32];   // per-CTA phi partials (30, padded to 32)
__device__ unsigned g_cnt;
__device__ volatile unsigned g_phase;

// ---------------- dynamic shared memory layout ----------------
struct Smem {
    __half Ws[32][KP];                 // persistent weight slice     197120 B
    union {
        __half xsw[8][2][16][40];      // per-warp x staging           20480 B
        float  redA[4][2][16][33];     // K-split reduction            16896 B
    } u;
    float gates[32][32];               // reduced gate tile             4096 B
    float cst[32][8];                  // persistent cell state         1024 B
    float hs[32][8];                   // fp32 h slice                  1024 B
    float Wg[32][8];                   // W_g slice (30 used)           1024 B
    float biasv[32];                   // b_ih + b_hh per local col      128 B
    float bgs[32];                     // b_g (30 used)                  128 B
    float predbuf[8][32];              // phi reduce stage               1024 B
    float phired[32];                  // reduced phi (30 used)           128 B
    float wbuf[SS];                    // attention weights              2048 B
    float ksi[16];                     // persistent ksi                   64 B
    float rbeta[16];                   // 1/beta                           64 B
    float alpha[16];                   // softmax alpha                    64 B
};

// ---------------- grid barrier (all 128 CTAs co-resident) ----------------
__device__ __forceinline__ void gridbar(unsigned& lp) {
    lp++;
    __syncthreads();
    if (threadIdx.x == 0) {
        __threadfence();
        unsigned old = atomicAdd(&g_cnt, 1u);
        if (old == NCTA - 1u) {
            atomicExch(&g_cnt, 0u);
            __threadfence();
            g_phase = lp;
        } else {
            while (g_phase < lp) __nanosleep(64);
        }
        __threadfence();
    }
    __syncthreads();
}

// ---------------- prep: fp32 -> fp16 conversions + state reset ----------------
__global__ void tts_prep(const float* __restrict__ in, const float* __restrict__ mem) {
    const int tid = blockIdx.x * blockDim.x + threadIdx.x;
    const int np  = gridDim.x * blockDim.x;
    const int N1  = BB * TT * DD;
    for (int i = tid; i < N1; i += np) g_in[i]  = __float2half(in[i]);
    for (int i = tid; i < N1; i += np) g_mem[i] = __float2half(mem[i]);
    for (int i = tid; i < BB * DD; i += np) {
        g_ctx[i]  = __float2half(0.f);
        g_h[0][i] = __float2half(0.f);
        g_h[1][i] = __float2half(0.f);
    }
    if (tid == 0) { g_cnt = 0u; g_phase = 0u; }
}

#define MMA_16816(ac, A0, A1, A2, A3, B0, B1)                               \
    asm volatile(                                                           \
        "mma.sync.aligned.m16n8k16.row.col.f32.f16.f16.f32 "                \
        "{%0,%1,%2,%3}, {%4,%5,%6,%7}, {%8,%9}, {%0,%1,%2,%3};"             \
        : "+f"((ac)[0]), "+f"((ac)[1]), "+f"((ac)[2]), "+f"((ac)[3])        \
        : "r"(A0), "r"(A1), "r"(A2), "r"(A3), "r"(B0), "r"(B1))

__device__ __forceinline__ float sigf(float x) {
    return __fdividef(1.f, 1.f + __expf(-x));
}

// ---------------- main persistent kernel ----------------
__global__ void __launch_bounds__(NTHR, 1) tts_main(
    const float* __restrict__ W_ih, const float* __restrict__ W_hh,
    const float* __restrict__ b_ih, const float* __restrict__ b_hh,
    const float* __restrict__ W_g,  const float* __restrict__ b_g,
    const int*   __restrict__ lens, float* __restrict__ out)
{
    extern __shared__ char smraw[];
    Smem& sm = *reinterpret_cast<Smem*>(smraw);
    const int tid  = threadIdx.x;
    const int cta  = blockIdx.x;
    const int wid  = tid >> 5;
    const int lane = tid & 31;

    const size_t ALIGN_OFF = (size_t)BB * DD;                      // 32768
    const size_t TERM_OFF  = ALIGN_OFF + (size_t)BB * TT * SS;     // 8421376

    // ---- one-time init ----
    for (int i = tid; i < 32 * K3; i += NTHR) {
        int c = i / K3, k = i - c * K3;
        int gcol = (c >> 3) * DD + cta * 8 + (c & 7);
        float wv = (k < 2048) ? W_ih[(size_t)gcol * 2048 + k]
                              : W_hh[(size_t)gcol * DD + (k - 2048)];
        sm.Ws[c][k] = __float2half(wv);
    }
    if (tid < 240) {
        int j = tid >> 3, uu = tid & 7;
        sm.Wg[j][uu] = W_g[(size_t)j * DD + cta * 8 + uu];
    }
    if (tid < 32) {
        int gcol = (tid >> 3) * DD + cta * 8 + (tid & 7);
        sm.biasv[tid] = b_ih[gcol] + b_hh[gcol];
    }
    if (tid < 30) sm.bgs[tid] = b_g[tid];
    { int b2 = tid >> 3, uu = tid & 7; sm.cst[b2][uu] = 0.f; }
    if (tid < 16) { sm.ksi[tid] = 0.f; sm.rbeta[tid] = 0.f; sm.alpha[tid] = 0.f; }
    __syncthreads();

    // warp roles for the gate GEMM
    const int bt = wid & 1;          // batch-half (rows bt*16 .. +16)
    const int kq = wid >> 1;         // K-quarter  (k in [kq*768, +768))
    const int gg = lane >> 2;        // mma group id (0..7)
    const int tg = lane & 3;         // thread-in-group (0..3)
    __half (&xw)[2][16][40] = sm.u.xsw[wid];
    // x staging load roles
    const int xrow = lane >> 1;              // 0..15
    const int xb   = bt * 16 + xrow;         // global batch
    const int xo   = (lane & 1) * 16;        // half-offset within 32-half chunk

    // phase B/C roles
    const int b  = cta & 31;     // batch
    const int dg = cta >> 5;     // d-slice (0..3) of 256

    unsigned lp = 0;

    for (int t = 0; t < TT; ++t) {
        const int p = t & 1;

        // ================= Phase A : gate GEMM =================
        float acc[16];
        #pragma unroll
        for (int i = 0; i < 16; ++i) acc[i] = 0.f;

        auto xsrc = [&](int kc) -> const __half* {
            int kk = kq * 768 + kc * 32;
            if (kk < 1024) return g_in  + ((size_t)xb * TT + t) * DD + kk;
            if (kk < 2048) return g_ctx + xb * DD + (kk - 1024);
            return g_h[p] + xb * DD + (kk - 2048);
        };

        uint4 ra, rb;
        {   // prologue: chunk0 -> buf0, chunk1 -> regs
            const __half* sp = xsrc(0);
            ra = __ldcg((const uint4*)(sp + xo));
            rb = __ldcg((const uint4*)(sp + xo + 8));
            *(uint4*)&xw[0][xrow][xo]     = ra;
            *(uint4*)&xw[0][xrow][xo + 8] = rb;
            sp = xsrc(1);
            ra = __ldcg((const uint4*)(sp + xo));
            rb = __ldcg((const uint4*)(sp + xo + 8));
        }
        __syncwarp();

        #pragma unroll 1
        for (int kc = 0; kc < 24; ++kc) {
            const int buf = kc & 1;
            const int k0  = kq * 768 + kc * 32;
            // compute 2 k-tiles from buf
            #pragma unroll
            for (int kt = 0; kt < 2; ++kt) {
                const int kb = kt * 16;
                unsigned a0 = *(const unsigned*)&xw[buf][gg    ][kb + 2 * tg];
                unsigned a1 = *(const unsigned*)&xw[buf][gg + 8][kb + 2 * tg];
                unsigned a2 = *(const unsigned*)&xw[buf][gg    ][kb + 2 * tg + 8];
                unsigned a3 = *(const unsigned*)&xw[buf][gg + 8][kb + 2 * tg + 8];
                const int kg = k0 + kb;
                #pragma unroll
                for (int nt = 0; nt < 4; ++nt) {
                    unsigned b0 = *(const unsigned*)&sm.Ws[nt * 8 + gg][kg + 2 * tg];
                    unsigned b1 = *(const unsigned*)&sm.Ws[nt * 8 + gg][kg + 2 * tg + 8];
                    MMA_16816(acc + nt * 4, a0, a1, a2, a3, b0, b1);
                }
            }
            if (kc + 1 < 24) {   // stage chunk kc+1 (in regs) into other buffer
                *(uint4*)&xw[buf ^ 1][xrow][xo]     = ra;
                *(uint4*)&xw[buf ^ 1][xrow][xo + 8] = rb;
            }
            if (kc + 2 < 24) {   // prefetch chunk kc+2
                const __half* sp = xsrc(kc + 2);
                ra = __ldcg((const uint4*)(sp + xo));
                rb = __ldcg((const uint4*)(sp + xo + 8));
            }
            __syncwarp();
        }
        __syncthreads();

        // K-split reduction: store frags, reduce over kq in fixed order
        #pragma unroll
        for (int nt = 0; nt < 4; ++nt) {
            #pragma unroll
            for (int i = 0; i < 4; ++i) {
                int r = gg + ((i >> 1) << 3);
                int c = nt * 8 + tg * 2 + (i & 1);
                sm.u.redA[kq][bt][r][c] = acc[nt * 4 + i];
            }
        }
        __syncthreads();
        #pragma unroll
        for (int rep = 0; rep < 4; ++rep) {
            int f = tid + rep * 256;               // 0..1023
            int bt2 = f >> 9, q = f & 511, r = q >> 5, c = q & 31;
            float v = sm.u.redA[0][bt2][r][c] + sm.u.redA[1][bt2][r][c]
                    + sm.u.redA[2][bt2][r][c] + sm.u.redA[3][bt2][r][c];
            sm.gates[bt2 * 16 + r][c] = v;
        }
        __syncthreads();

        // ---- LSTM cell (thread = (batch, unit)) ----
        {
            int bb = tid >> 3, uu = tid & 7;
            float ig = sm.gates[bb][uu]      + sm.biasv[uu];
            float fg = sm.gates[bb][8 + uu]  + sm.biasv[8 + uu];
            float gv = sm.gates[bb][16 + uu] + sm.biasv[16 + uu];
            float og = sm.gates[bb][24 + uu] + sm.biasv[24 + uu];
            float cn = sigf(fg) * sm.cst[bb][uu] + sigf(ig) * tanhf(gv);
            sm.cst[bb][uu] = cn;
            float hv = sigf(og) * tanhf(cn);
            sm.hs[bb][uu] = hv;
            g_h[p ^ 1][bb * DD + cta * 8 + uu] = __float2half(hv);
        }
        __syncthreads();

        // ---- phi partials over this CTA's 8 units ----
        #pragma unroll
        for (int it = 0; it < 4; ++it) {
            int idx = tid + it * 256;
            if (idx < 960) {
                int pb = idx / 30, j = idx - pb * 30;
                float s = 0.f;
                #pragma unroll
                for (int uu = 0; uu < 8; ++uu) s += sm.hs[pb][uu] * sm.Wg[j][uu];
                g_phipart[cta][pb][j] = s;
            }
        }

        gridbar(lp);   // phi partials + h visible everywhere

        // ================= Phase B : mixture head (batch b) =================
        if (tid < 240) {
            int j = tid % 30, cg = tid / 30;
            float s = 0.f;
            int c0 = cg * 16;
            #pragma unroll 4
            for (int c = 0; c < 16; ++c) s += __ldcg(&g_phipart[c0 + c][b][j]);
            sm.predbuf[cg][j] = s;
        }
        __syncthreads();
        if (tid < 30) {
            float s = sm.bgs[tid];
            #pragma unroll
            for (int cg = 0; cg < 8; ++cg) s += sm.predbuf[cg][tid];
            sm.phired[tid] = s;
        }
        __syncthreads();
        if (tid == 0) {
            float pc[MM], amax = -1e30f;
            #pragma unroll
            for (int m = 0; m < MM; ++m) { pc[m] = sm.phired[20 + m]; amax = fmaxf(amax, pc[m]); }
            float ssum = 0.f;
            #pragma unroll
            for (int m = 0; m < MM; ++m) { float e = __expf(pc[m] - amax); pc[m] = e; ssum += e; }
            float rs = __fdividef(1.f, ssum);
            #pragma unroll
            for (int m = 0; m < MM; ++m) {
                sm.ksi[m]  += __expf(sm.phired[m]);
                sm.rbeta[m] = __expf(-sm.phired[10 + m]);
                sm.alpha[m] = pc[m] * rs;
            }
        }
        __syncthreads();

        // attention weights w[s]
        #pragma unroll
        for (int rep = 0; rep < 2; ++rep) {
            int s = tid + rep * 256;
            float su = (float)s;
            float t1 = 0.f, t2 = 0.f;
            #pragma unroll
            for (int m = 0; m < MM; ++m) {
                float a = sm.alpha[m], kk = sm.ksi[m], rv = sm.rbeta[m];
                float zr = (su + 1.5f - kk) * rv;
                float zl = (su + 0.5f - kk) * rv;
                t1 += __fdividef(a, 1.f + __expf(-zr));
                t2 += __fdividef(a, 1.f + __expf(-zl));
            }
            sm.wbuf[s] = t1 - t2;
        }
        __syncthreads();

        // termination output (last step only): 1 - term1 at s = len-1
        if (t == TT - 1 && dg == 0 && tid == 0) {
            int sl = lens[b] - 1;
            float su = (float)sl;
            float t1 = 0.f;
            #pragma unroll
            for (int m = 0; m < MM; ++m) {
                float zr = (su + 1.5f - sm.ksi[m]) * sm.rbeta[m];
                t1 += __fdividef(sm.alpha[m], 1.f + __expf(-zr));
            }
            out[TERM_OFF + b] = 1.f - t1;
        }

        // ================= Phase C : ctx = w @ memory =================
        {
            int d = dg * 256 + tid;
            const __half* mp = g_mem + (size_t)b * SS * DD + d;
            float accv = 0.f;
            #pragma unroll 8
            for (int s = 0; s < SS; ++s)
                accv += sm.wbuf[s] * __half2float(__ldg(mp + (size_t)s * DD));
            g_ctx[b * DD + d] = __float2half(accv);
            if (t == TT - 1) out[b * DD + d] = accv;
        }
        if (dg == 0) {
            size_t base = ALIGN_OFF + ((size_t)b * TT + t) * SS;
            out[base + tid]       = sm.wbuf[tid];
            out[base + tid + 256] = sm.wbuf[tid + 256];
        }

        gridbar(lp);   // ctx visible before next step's GEMM
    }
}

extern "C" void kernel_launch(void* const* d_in, const int* in_sizes, int n_in,
                              void* d_out, int out_size) {
    const float* in_h   = (const float*)d_in[0];
    const float* mem    = (const float*)d_in[1];
    const int*   lens   = (const int*)d_in[2];
    const float* W_ih   = (const float*)d_in[3];
    const float* W_hh   = (const float*)d_in[4];
    const float* b_ih   = (const float*)d_in[5];
    const float* b_hh   = (const float*)d_in[6];
    const float* W_g    = (const float*)d_in[7];
    const float* b_g    = (const float*)d_in[8];
    float* out = (float*)d_out;

    static int smem_set = 0;
    if (!smem_set) {
        cudaFuncSetAttribute(tts_main, cudaFuncAttributeMaxDynamicSharedMemorySize,
                             (int)sizeof(Smem));
        smem_set = 1;
    }

    tts_prep<<<1024, 256>>>(in_h, mem);
    tts_main<<<NCTA, NTHR, sizeof(Smem)>>>(W_ih, W_hh, b_ih, b_hh, W_g, b_g, lens, out);
}

// round 4
// speedup vs baseline: 1.5418x; 1.5418x over previous
#include <cuda_runtime.h>
#include <cuda_fp16.h>
#include <math.h>
#include <stdint.h>

#define BB   32
#define TT   512
#define SS   512
#define DD   1024
#define MM   10
#define K3   3072
#define KP   3080      // padded K stride (halves) for Ws: conflict-free B-frag loads
#define NCTA 128
#define NTHR 256

// ---------------- static device scratch (allocations are forbidden) ----------------
__device__ __half  g_in[BB * TT * DD];          // fp16 copy of input_h_c
__device__ __half  g_mem[BB * SS * DD];         // fp16 copy of memory
__device__ __half  g_ctx[BB * DD];              // ctx_t (fp16), produced by phase C
__device__ __half  g_h[2][BB * DD];             // double-buffered h (fp16)
__device__ float   g_phipart[2][NCTA][BB][32];  // per-CTA phi partials, dbl-buffered
__device__ unsigned g_arrive[NCTA];             // flag barrier: per-CTA arrival
__device__ unsigned g_release;                  // flag barrier: release word
__device__ unsigned g_cctr;                     // phase-C completion counter (monotonic)

// ---------------- dynamic shared memory layout ----------------
struct Smem {
    __half Ws[32][KP];                 // persistent weight slice     197120 B
    union {
        __half xsw[8][2][16][40];      // per-warp x staging           20480 B
        float  redA[4][2][16][33];     // K-split reduction            16896 B
        float  cred[8][256];           // phase-C cross-warp reduce     8192 B
    } u;
    float gates[32][32];               // reduced gate tile             4096 B
    float cst[32][8];                  // persistent cell state         1024 B
    float hs[32][8];                   // fp32 h slice                  1024 B
    float Wg[32][8];                   // W_g slice (30 used)           1024 B
    float biasv[32];                   // b_ih + b_hh per local col      128 B
    float bgs[32];                     // b_g (30 used)                  128 B
    float predbuf[8][32];              // phi reduce stage               1024 B
    float phired[32];                  // reduced phi (30 used)           128 B
    float wbuf[SS];                    // attention weights              2048 B
    float ksi[16];                     // persistent ksi                   64 B
    float rbeta[16];                   // 1/beta                           64 B
    float alpha[16];                   // softmax alpha                    64 B
};

// ---------------- flag-based grid barrier (all 128 CTAs co-resident) ----------------
// Arrival: per-CTA distinct flag (no atomic contention). CTA0's first 128 threads
// poll the 128 flags in parallel, then CTA0 publishes a single release word.
__device__ __forceinline__ void flagbar(int cta, int tid, unsigned want) {
    __syncthreads();
    if (cta == 0) {
        if (tid == 0) {
            __threadfence();
            *(volatile unsigned*)&g_arrive[0] = want;
        }
        if (tid < NCTA) {
            while (*(volatile unsigned*)&g_arrive[tid] < want) { }
        }
        __syncthreads();
        if (tid == 0) {
            __threadfence();
            *(volatile unsigned*)&g_release = want;
        }
    } else {
        if (tid == 0) {
            __threadfence();
            *(volatile unsigned*)&g_arrive[cta] = want;
            while (*(volatile unsigned*)&g_release < want) { }
            __threadfence();
        }
    }
    __syncthreads();
}

// ---------------- prep: fp32 -> fp16 conversions + state reset ----------------
__global__ void tts_prep(const float* __restrict__ in, const float* __restrict__ mem) {
    const int tid = blockIdx.x * blockDim.x + threadIdx.x;
    const int np  = gridDim.x * blockDim.x;
    const int N1  = BB * TT * DD;
    for (int i = tid; i < N1; i += np) g_in[i]  = __float2half(in[i]);
    for (int i = tid; i < N1; i += np) g_mem[i] = __float2half(mem[i]);
    for (int i = tid; i < BB * DD; i += np) {
        g_ctx[i]  = __float2half(0.f);
        g_h[0][i] = __float2half(0.f);
        g_h[1][i] = __float2half(0.f);
    }
    if (tid < NCTA) g_arrive[tid] = 0u;
    if (tid == 0) { g_release = 0u; g_cctr = 0u; }
}

#define MMA_16816(ac, A0, A1, A2, A3, B0, B1)                               \
    asm volatile(                                                           \
        "mma.sync.aligned.m16n8k16.row.col.f32.f16.f16.f32 "                \
        "{%0,%1,%2,%3}, {%4,%5,%6,%7}, {%8,%9}, {%0,%1,%2,%3};"             \
        : "+f"((ac)[0]), "+f"((ac)[1]), "+f"((ac)[2]), "+f"((ac)[3])        \
        : "r"(A0), "r"(A1), "r"(A2), "r"(A3), "r"(B0), "r"(B1))

__device__ __forceinline__ float sigf(float x) {
    return __fdividef(1.f, 1.f + __expf(-x));
}

// ---------------- main persistent kernel ----------------
__global__ void __launch_bounds__(NTHR, 1) tts_main(
    const float* __restrict__ W_ih, const float* __restrict__ W_hh,
    const float* __restrict__ b_ih, const float* __restrict__ b_hh,
    const float* __restrict__ W_g,  const float* __restrict__ b_g,
    const int*   __restrict__ lens, float* __restrict__ out)
{
    extern __shared__ char smraw[];
    Smem& sm = *reinterpret_cast<Smem*>(smraw);
    const int tid  = threadIdx.x;
    const int cta  = blockIdx.x;
    const int wid  = tid >> 5;
    const int lane = tid & 31;

    const size_t ALIGN_OFF = (size_t)BB * DD;                      // 32768
    const size_t TERM_OFF  = ALIGN_OFF + (size_t)BB * TT * SS;     // 8421376

    // ---- one-time init ----
    for (int i = tid; i < 32 * K3; i += NTHR) {
        int c = i / K3, k = i - c * K3;
        int gcol = (c >> 3) * DD + cta * 8 + (c & 7);
        float wv = (k < 2048) ? W_ih[(size_t)gcol * 2048 + k]
                              : W_hh[(size_t)gcol * DD + (k - 2048)];
        sm.Ws[c][k] = __float2half(wv);
    }
    if (tid < 240) {
        int j = tid >> 3, uu = tid & 7;
        sm.Wg[j][uu] = W_g[(size_t)j * DD + cta * 8 + uu];
    }
    if (tid < 32) {
        int gcol = (tid >> 3) * DD + cta * 8 + (tid & 7);
        sm.biasv[tid] = b_ih[gcol] + b_hh[gcol];
    }
    if (tid < 30) sm.bgs[tid] = b_g[tid];
    { int b2 = tid >> 3, uu = tid & 7; sm.cst[b2][uu] = 0.f; }
    if (tid < 16) { sm.ksi[tid] = 0.f; sm.rbeta[tid] = 0.f; sm.alpha[tid] = 0.f; }
    __syncthreads();

    // warp roles for the gate GEMM
    const int bt = wid & 1;          // batch-half (rows bt*16 .. +16)
    const int kq = wid >> 1;         // K-quarter  (k in [kq*768, +768))
    const int gg = lane >> 2;        // mma group id (0..7)
    const int tg = lane & 3;         // thread-in-group (0..3)
    __half (&xw)[2][16][40] = sm.u.xsw[wid];
    const int xrow = lane >> 1;              // 0..15
    const int xb   = bt * 16 + xrow;         // global batch
    const int xo   = (lane & 1) * 16;        // half-offset within 32-half chunk
    // ctx region is k in [1024,2048): touched by kq==1 (chunks 8..23) and
    // kq==2 (chunks 0..15). For kq==2 we reorder so h-chunks (16..23) run
    // first; for both, the wait happens before prefetching sequence index 8.
    const bool needs_ctx = (kq == 1 || kq == 2);

    // phase B/C roles
    const int b  = cta & 31;     // batch
    const int dg = cta >> 5;     // d-slice (0..3) of 256

    for (int t = 0; t < TT; ++t) {
        const int p = t & 1;

        // ================= Phase A : gate GEMM =================
        float acc[16];
        #pragma unroll
        for (int i = 0; i < 16; ++i) acc[i] = 0.f;

        auto seqmap = [&](int i) -> int {
            return (kq == 2) ? ((i < 8) ? i + 16 : i - 8) : i;
        };
        auto xsrc = [&](int kc) -> const __half* {
            int kk = kq * 768 + kc * 32;
            if (kk < 1024) return g_in  + ((size_t)xb * TT + t) * DD + kk;
            if (kk < 2048) return g_ctx + xb * DD + (kk - 1024);
            return g_h[p] + xb * DD + (kk - 2048);
        };

        uint4 ra, rb;
        {   // prologue: seq(0) -> buf0, seq(1) -> regs (both guaranteed non-ctx)
            const __half* sp = xsrc(seqmap(0));
            ra = __ldcg((const uint4*)(sp + xo));
            rb = __ldcg((const uint4*)(sp + xo + 8));
            *(uint4*)&xw[0][xrow][xo]     = ra;
            *(uint4*)&xw[0][xrow][xo + 8] = rb;
            sp = xsrc(seqmap(1));
            ra = __ldcg((const uint4*)(sp + xo));
            rb = __ldcg((const uint4*)(sp + xo + 8));
        }
        __syncwarp();

        #pragma unroll 1
        for (int i = 0; i < 24; ++i) {
            const int buf = i & 1;
            const int kc  = seqmap(i);
            const int k0  = kq * 768 + kc * 32;
            #pragma unroll
            for (int kt = 0; kt < 2; ++kt) {
                const int kb = kt * 16;
                unsigned a0 = *(const unsigned*)&xw[buf][gg    ][kb + 2 * tg];
                unsigned a1 = *(const unsigned*)&xw[buf][gg + 8][kb + 2 * tg];
                unsigned a2 = *(const unsigned*)&xw[buf][gg    ][kb + 2 * tg + 8];
                unsigned a3 = *(const unsigned*)&xw[buf][gg + 8][kb + 2 * tg + 8];
                const int kg = k0 + kb;
                #pragma unroll
                for (int nt = 0; nt < 4; ++nt) {
                    unsigned b0 = *(const unsigned*)&sm.Ws[nt * 8 + gg][kg + 2 * tg];
                    unsigned b1 = *(const unsigned*)&sm.Ws[nt * 8 + gg][kg + 2 * tg + 8];
                    MMA_16816(acc + nt * 4, a0, a1, a2, a3, b0, b1);
                }
            }
            if (i + 1 < 24) {
                *(uint4*)&xw[buf ^ 1][xrow][xo]     = ra;
                *(uint4*)&xw[buf ^ 1][xrow][xo + 8] = rb;
            }
            if (i + 2 < 24) {
                if (needs_ctx && i == 6) {
                    // ctx chunks start at sequence index 8; wait for all CTAs'
                    // phase C of step t-1 before prefetching them.
                    const unsigned want = (unsigned)(NCTA * t);
                    while (*(volatile unsigned*)&g_cctr < want) { }
                    __threadfence();
                }
                const __half* sp = xsrc(seqmap(i + 2));
                ra = __ldcg((const uint4*)(sp + xo));
                rb = __ldcg((const uint4*)(sp + xo + 8));
            }
            __syncwarp();
        }
        __syncthreads();

        // K-split reduction: store frags, reduce over kq in fixed order
        #pragma unroll
        for (int nt = 0; nt < 4; ++nt) {
            #pragma unroll
            for (int i = 0; i < 4; ++i) {
                int r = gg + ((i >> 1) << 3);
                int c = nt * 8 + tg * 2 + (i & 1);
                sm.u.redA[kq][bt][r][c] = acc[nt * 4 + i];
            }
        }
        __syncthreads();
        #pragma unroll
        for (int rep = 0; rep < 4; ++rep) {
            int f = tid + rep * 256;               // 0..1023
            int bt2 = f >> 9, q = f & 511, r = q >> 5, c = q & 31;
            float v = sm.u.redA[0][bt2][r][c] + sm.u.redA[1][bt2][r][c]
                    + sm.u.redA[2][bt2][r][c] + sm.u.redA[3][bt2][r][c];
            sm.gates[bt2 * 16 + r][c] = v;
        }
        __syncthreads();

        // ---- LSTM cell (thread = (batch, unit)) ----
        {
            int bb = tid >> 3, uu = tid & 7;
            float ig = sm.gates[bb][uu]      + sm.biasv[uu];
            float fg = sm.gates[bb][8 + uu]  + sm.biasv[8 + uu];
            float gv = sm.gates[bb][16 + uu] + sm.biasv[16 + uu];
            float og = sm.gates[bb][24 + uu] + sm.biasv[24 + uu];
            float cn = sigf(fg) * sm.cst[bb][uu] + sigf(ig) * tanhf(gv);
            sm.cst[bb][uu] = cn;
            float hv = sigf(og) * tanhf(cn);
            sm.hs[bb][uu] = hv;
            g_h[p ^ 1][bb * DD + cta * 8 + uu] = __float2half(hv);
        }
        __syncthreads();

        // ---- phi partials over this CTA's 8 units (double-buffered by t&1) ----
        #pragma unroll
        for (int it = 0; it < 4; ++it) {
            int idx = tid + it * 256;
            if (idx < 960) {
                int pb = idx / 30, j = idx - pb * 30;
                float s = 0.f;
                #pragma unroll
                for (int uu = 0; uu < 8; ++uu) s += sm.hs[pb][uu] * sm.Wg[j][uu];
                g_phipart[p][cta][pb][j] = s;
            }
        }

        flagbar(cta, tid, (unsigned)(t + 1));   // phi + h visible everywhere

        // ================= Phase B : mixture head (batch b) =================
        if (tid < 240) {
            int j = tid % 30, cg = tid / 30;
            float s = 0.f;
            int c0 = cg * 16;
            #pragma unroll 4
            for (int c = 0; c < 16; ++c) s += __ldcg(&g_phipart[p][c0 + c][b][j]);
            sm.predbuf[cg][j] = s;
        }
        __syncthreads();
        if (tid < 30) {
            float s = sm.bgs[tid];
            #pragma unroll
            for (int cg = 0; cg < 8; ++cg) s += sm.predbuf[cg][tid];
            sm.phired[tid] = s;
        }
        __syncthreads();
        if (tid == 0) {
            float pc[MM], amax = -1e30f;
            #pragma unroll
            for (int m = 0; m < MM; ++m) { pc[m] = sm.phired[20 + m]; amax = fmaxf(amax, pc[m]); }
            float ssum = 0.f;
            #pragma unroll
            for (int m = 0; m < MM; ++m) { float e = __expf(pc[m] - amax); pc[m] = e; ssum += e; }
            float rs = __fdividef(1.f, ssum);
            #pragma unroll
            for (int m = 0; m < MM; ++m) {
                sm.ksi[m]  += __expf(sm.phired[m]);
                sm.rbeta[m] = __expf(-sm.phired[10 + m]);
                sm.alpha[m] = pc[m] * rs;
            }
        }
        __syncthreads();

        // attention weights w[s]
        #pragma unroll
        for (int rep = 0; rep < 2; ++rep) {
            int s = tid + rep * 256;
            float su = (float)s;
            float t1 = 0.f, t2 = 0.f;
            #pragma unroll
            for (int m = 0; m < MM; ++m) {
                float a = sm.alpha[m], kk = sm.ksi[m], rv = sm.rbeta[m];
                float zr = (su + 1.5f - kk) * rv;
                float zl = (su + 0.5f - kk) * rv;
                t1 += __fdividef(a, 1.f + __expf(-zr));
                t2 += __fdividef(a, 1.f + __expf(-zl));
            }
            sm.wbuf[s] = t1 - t2;
        }
        __syncthreads();

        // alignment output for step t (issue early so stores overlap phase C)
        if (dg == 0) {
            size_t base = ALIGN_OFF + ((size_t)b * TT + t) * SS;
            out[base + tid]       = sm.wbuf[tid];
            out[base + tid + 256] = sm.wbuf[tid + 256];
        }
        // termination output (last step only): 1 - term1 at s = len-1
        if (t == TT - 1 && dg == 0 && tid == 0) {
            int sl = lens[b] - 1;
            float su = (float)sl;
            float t1 = 0.f;
            #pragma unroll
            for (int m = 0; m < MM; ++m) {
                float zr = (su + 1.5f - sm.ksi[m]) * sm.rbeta[m];
                t1 += __fdividef(sm.alpha[m], 1.f + __expf(-zr));
            }
            out[TERM_OFF + b] = 1.f - t1;
        }

        // ================= Phase C : ctx = w @ memory (vectorized) =================
        {
            // warp wid handles s in [wid*64, wid*64+64); lane owns 8 consecutive d
            float accv[8];
            #pragma unroll
            for (int j = 0; j < 8; ++j) accv[j] = 0.f;
            const __half* mpb = g_mem + ((size_t)b * SS + wid * 64) * DD
                              + dg * 256 + lane * 8;
            const float* wb = &sm.wbuf[wid * 64];
            #pragma unroll 4
            for (int i = 0; i < 64; ++i) {
                float wv = wb[i];
                uint4 v = __ldg((const uint4*)(mpb + (size_t)i * DD));
                const __half2* h2 = (const __half2*)&v;
                #pragma unroll
                for (int j = 0; j < 4; ++j) {
                    float2 f = __half22float2(h2[j]);
                    accv[2 * j]     += wv * f.x;
                    accv[2 * j + 1] += wv * f.y;
                }
            }
            float* cr = sm.u.cred[wid];
            #pragma unroll
            for (int j = 0; j < 8; ++j) cr[lane * 8 + j] = accv[j];
        }
        __syncthreads();
        {
            int d = tid;                       // 0..255 within this CTA's d-slice
            float s0 = 0.f;
            #pragma unroll
            for (int w = 0; w < 8; ++w) s0 += sm.u.cred[w][d];
            g_ctx[b * DD + dg * 256 + d] = __float2half(s0);
            if (t == TT - 1) out[b * DD + dg * 256 + d] = s0;
        }
        __syncthreads();
        if (tid == 0) {
            __threadfence();
            atomicAdd(&g_cctr, 1u);            // phase-C completion (replaces barrier2)
        }
    }
}

extern "C" void kernel_launch(void* const* d_in, const int* in_sizes, int n_in,
                              void* d_out, int out_size) {
    const float* in_h   = (const float*)d_in[0];
    const float* mem    = (const float*)d_in[1];
    const int*   lens   = (const int*)d_in[2];
    const float* W_ih   = (const float*)d_in[3];
    const float* W_hh   = (const float*)d_in[4];
    const float* b_ih   = (const float*)d_in[5];
    const float* b_hh   = (const float*)d_in[6];
    const float* W_g    = (const float*)d_in[7];
    const float* b_g    = (const float*)d_in[8];
    float* out = (float*)d_out;

    cudaFuncSetAttribute(tts_main, cudaFuncAttributeMaxDynamicSharedMemorySize,
                         (int)sizeof(Smem));

    tts_prep<<<1024, 256>>>(in_h, mem);
    tts_main<<<NCTA, NTHR, sizeof(Smem)>>>(W_ih, W_hh, b_ih, b_hh, W_g, b_g, lens, out);
}